// round 1
// baseline (speedup 1.0000x reference)
#include <cuda_runtime.h>
#include <cuda_bf16.h>

#define NNODES 50000
#define NEDGES 400000
#define DDIM   512
#define NEG_SLOPE 0.01f
#define FILL 2.0f

// Scratch: H = X @ W for the current conv (102.4 MB), plus degree/norm arrays.
__device__ float g_H[(size_t)NNODES * DDIM];
__device__ float g_deg[NNODES];
__device__ float g_dis[NNODES];

// ---------------------------------------------------------------------------
// Degree / symmetric-norm precompute
// ---------------------------------------------------------------------------
__global__ void init_deg_kernel() {
    int n = blockIdx.x * blockDim.x + threadIdx.x;
    if (n < NNODES) g_deg[n] = FILL;  // self-loop weight (improved=True)
}

__global__ void accum_deg_kernel(const int* __restrict__ dst,
                                 const float* __restrict__ w) {
    int e = blockIdx.x * blockDim.x + threadIdx.x;
    if (e < NEDGES) atomicAdd(&g_deg[dst[e]], w[e]);
}

__global__ void calc_dis_kernel() {
    int n = blockIdx.x * blockDim.x + threadIdx.x;
    if (n < NNODES) {
        float d = g_deg[n];
        g_dis[n] = (d > 0.0f) ? rsqrtf(d) : 0.0f;
    }
}

// ---------------------------------------------------------------------------
// SGEMM: C[M,512] = A[M,512] @ B[512,512], row-major, fp32.
// 128x128 block tile, BK=16, 256 threads, 8x8 per-thread micro-tile.
// Only M (=50000) is ragged; K and N are multiples of the tile.
// ---------------------------------------------------------------------------
__global__ __launch_bounds__(256, 2) void sgemm_kernel(
    const float* __restrict__ A, const float* __restrict__ B,
    float* __restrict__ C, int M)
{
    const int K = DDIM, Nn = DDIM;
    __shared__ float As[16][128];   // transposed A tile: As[k][m]
    __shared__ float Bs[16][128];   // Bs[k][n]

    const int tid = threadIdx.x;
    const int blockRow = blockIdx.y * 128;
    const int blockCol = blockIdx.x * 128;

    const int aRow = tid / 4;           // 0..63 (stride 64 for second half)
    const int aCol = (tid % 4) * 4;     // 0,4,8,12
    const int bRow = tid / 32;          // 0..7 (stride 8)
    const int bCol = (tid % 32) * 4;    // 0..124

    const int threadRow = (tid / 16) * 8;   // 0..120
    const int threadCol = (tid % 16) * 8;   // 0..120

    float acc[8][8];
    #pragma unroll
    for (int i = 0; i < 8; i++)
        #pragma unroll
        for (int j = 0; j < 8; j++) acc[i][j] = 0.0f;

    for (int k0 = 0; k0 < K; k0 += 16) {
        // Load A tile (transposed into shared)
        #pragma unroll
        for (int i = 0; i < 2; i++) {
            int r = blockRow + aRow + i * 64;
            float4 v = make_float4(0.f, 0.f, 0.f, 0.f);
            if (r < M)
                v = *(const float4*)(A + (size_t)r * K + k0 + aCol);
            As[aCol + 0][aRow + i * 64] = v.x;
            As[aCol + 1][aRow + i * 64] = v.y;
            As[aCol + 2][aRow + i * 64] = v.z;
            As[aCol + 3][aRow + i * 64] = v.w;
        }
        // Load B tile
        #pragma unroll
        for (int i = 0; i < 2; i++) {
            int r = k0 + bRow + i * 8;
            *(float4*)(&Bs[bRow + i * 8][bCol]) =
                *(const float4*)(B + (size_t)r * Nn + blockCol + bCol);
        }
        __syncthreads();

        #pragma unroll
        for (int kk = 0; kk < 16; kk++) {
            float regA[8], regB[8];
            *(float4*)(&regA[0]) = *(const float4*)(&As[kk][threadRow]);
            *(float4*)(&regA[4]) = *(const float4*)(&As[kk][threadRow + 4]);
            *(float4*)(&regB[0]) = *(const float4*)(&Bs[kk][threadCol]);
            *(float4*)(&regB[4]) = *(const float4*)(&Bs[kk][threadCol + 4]);
            #pragma unroll
            for (int i = 0; i < 8; i++)
                #pragma unroll
                for (int j = 0; j < 8; j++)
                    acc[i][j] = fmaf(regA[i], regB[j], acc[i][j]);
        }
        __syncthreads();
    }

    #pragma unroll
    for (int i = 0; i < 8; i++) {
        int r = blockRow + threadRow + i;
        if (r < M) {
            float* cp = C + (size_t)r * Nn + blockCol + threadCol;
            *(float4*)(cp)     = make_float4(acc[i][0], acc[i][1], acc[i][2], acc[i][3]);
            *(float4*)(cp + 4) = make_float4(acc[i][4], acc[i][5], acc[i][6], acc[i][7]);
        }
    }
}

// ---------------------------------------------------------------------------
// Edge scatter: O[dst] += dis[src]*w*dis[dst] * H[src]
// One edge per 128-thread block; each thread handles one float4 (4 cols)
// via a single 128-bit red.global.add (no return, 4x fewer atomic ops).
// ---------------------------------------------------------------------------
__global__ void scatter_edges_kernel(const int* __restrict__ src,
                                     const int* __restrict__ dst,
                                     const float* __restrict__ w,
                                     float* __restrict__ O)
{
    int e = blockIdx.x;
    int s = src[e];
    int d = dst[e];
    float coef = g_dis[s] * w[e] * g_dis[d];

    const float4* h = (const float4*)(g_H + (size_t)s * DDIM);
    float* o = O + (size_t)d * DDIM;

    int c = threadIdx.x;  // 0..127
    float4 v = h[c];
    asm volatile(
        "red.global.add.v4.f32 [%0], {%1, %2, %3, %4};"
        :: "l"(o + c * 4),
           "f"(coef * v.x), "f"(coef * v.y), "f"(coef * v.z), "f"(coef * v.w)
        : "memory");
}

// ---------------------------------------------------------------------------
// Finalize: add self-loop term (dis[n]^2 * FILL * H[n]) and apply leaky relu.
// Operates in float4 units over the whole [N, 512] slice.
// ---------------------------------------------------------------------------
__device__ __forceinline__ float leaky(float v) {
    return v >= 0.0f ? v : NEG_SLOPE * v;
}

__global__ void finalize_kernel(float* __restrict__ O) {
    size_t i = (size_t)blockIdx.x * blockDim.x + threadIdx.x;  // float4 index
    const size_t total = (size_t)NNODES * (DDIM / 4);
    if (i >= total) return;
    int n = (int)(i >> 7);  // / (512/4)
    float dn = g_dis[n];
    float sc = FILL * dn * dn;

    float4 h = ((const float4*)g_H)[i];
    float4 o = ((float4*)O)[i];
    o.x = leaky(o.x + sc * h.x);
    o.y = leaky(o.y + sc * h.y);
    o.z = leaky(o.z + sc * h.z);
    o.w = leaky(o.w + sc * h.w);
    ((float4*)O)[i] = o;
}

// ---------------------------------------------------------------------------
// Launch
// ---------------------------------------------------------------------------
extern "C" void kernel_launch(void* const* d_in, const int* in_sizes, int n_in,
                              void* d_out, int out_size)
{
    const float* x0   = (const float*)d_in[0];
    const float* x1   = (const float*)d_in[1];
    const float* x2   = (const float*)d_in[2];
    const int*   adj  = (const int*)d_in[3];    // [2, E] row-major
    const float* w    = (const float*)d_in[4];
    const float* Wmat = (const float*)d_in[5];
    const float* Wres = (const float*)d_in[6];
    float* out = (float*)d_out;

    const int* src = adj;            // adj_index[0]
    const int* dst = adj + NEDGES;   // adj_index[1]

    float* Hptr = nullptr;
    cudaGetSymbolAddress((void**)&Hptr, g_H);

    // Norm precompute (shared across the 3 convs)
    init_deg_kernel<<<(NNODES + 255) / 256, 256>>>();
    accum_deg_kernel<<<(NEDGES + 255) / 256, 256>>>(dst, w);
    calc_dis_kernel<<<(NNODES + 255) / 256, 256>>>();

    dim3 gemm_grid(DDIM / 128, (NNODES + 127) / 128);  // (4, 391)
    const float* xs[3] = {x0, x1, x2};

    const size_t slice = (size_t)NNODES * DDIM;
    const int fin_blocks = (int)((slice / 4 + 255) / 256);

    for (int t = 0; t < 3; t++) {
        float* O = out + (size_t)t * slice;
        // H = X @ W
        sgemm_kernel<<<gemm_grid, 256>>>(xs[t], Wmat, Hptr, NNODES);
        // O = X @ W_res (residual initializes the accumulator)
        sgemm_kernel<<<gemm_grid, 256>>>(xs[t], Wres, O, NNODES);
        // O += scatter(norm * H[src])
        scatter_edges_kernel<<<NEDGES, 128>>>(src, dst, w, O);
        // O = leaky(O + self_loop_norm * H)
        finalize_kernel<<<fin_blocks, 256>>>(O);
    }
}

// round 3
// speedup vs baseline: 1.3458x; 1.3458x over previous
#include <cuda_runtime.h>
#include <mma.h>
#include <cstdint>

using namespace nvcuda;

#define NNODES 50000
#define NEDGES 400000
#define DDIM   512
#define NEG_SLOPE 0.01f
#define FILL 2.0f

// ---------------------------------------------------------------------------
// Device scratch (static: no allocations allowed)
// ---------------------------------------------------------------------------
__device__ float g_H[(size_t)NNODES * DDIM];   // H = X @ W (102.4 MB)
__device__ float g_deg[NNODES];
__device__ float g_dis[NNODES];

// ---------------------------------------------------------------------------
// Degree / symmetric-norm precompute
// ---------------------------------------------------------------------------
__global__ void init_deg_kernel() {
    int n = blockIdx.x * blockDim.x + threadIdx.x;
    if (n < NNODES) g_deg[n] = FILL;
}
__global__ void accum_deg_kernel(const int* __restrict__ dst, const float* __restrict__ w) {
    int e = blockIdx.x * blockDim.x + threadIdx.x;
    if (e < NEDGES) atomicAdd(&g_deg[dst[e]], w[e]);
}
__global__ void calc_dis_kernel() {
    int n = blockIdx.x * blockDim.x + threadIdx.x;
    if (n < NNODES) {
        float d = g_deg[n];
        g_dis[n] = (d > 0.0f) ? rsqrtf(d) : 0.0f;
    }
}

// ---------------------------------------------------------------------------
// TF32 WMMA GEMM:  C[M, 1024] = X[M, 512] @ [W | Wres]
// CTA tile 128(M) x 128(N), BK = 32, 8 warps, warp tile 32x64 (2x4 wmma).
// Double-buffered cp.async. blockIdx.x in [0,8): tiles 0-3 -> H, 4-7 -> O.
// ---------------------------------------------------------------------------
#define MT 128
#define NT 128
#define BK 32
#define LDA (BK + 4)       // 36 floats per A row (pad vs bank conflicts)
#define LDB (NT + 4)       // 132 floats per B row
#define A_STAGE (MT * LDA) // 4608 floats
#define B_STAGE (BK * LDB) // 4224 floats
#define STAGE_FLOATS (A_STAGE + B_STAGE)
#define SMEM_FLOATS (2 * STAGE_FLOATS)          // 17664 floats = 70656 B
#define CHUNKS (DDIM / BK)                      // 16

__global__ __launch_bounds__(256) void gemm_tf32_wmma_kernel(
    const float* __restrict__ A,     // X slice [M, 512]
    const float* __restrict__ W,     // [512, 512] row-major
    const float* __restrict__ Wres,  // [512, 512] row-major
    float* __restrict__ H,           // [M, 512]
    float* __restrict__ O,           // [M, 512]
    int M)
{
    extern __shared__ float smem[];
    float* As = smem;                         // 2 stages of A
    float* Bs = smem + 2 * A_STAGE;           // 2 stages of B

    const int tid = threadIdx.x;
    const int wid = tid >> 5;
    const int m0 = blockIdx.y * MT;
    const int bx = blockIdx.x;                // 0..7

    const float* Bsrc = (bx < 4) ? W : Wres;
    const int ncol0 = (bx & 3) * NT;          // column offset within the 512-wide matrix
    float* outbase = (bx < 4) ? H : O;

    const int warp_m = wid & 3;               // 0..3 -> 32-row strip
    const int warp_n = wid >> 2;              // 0..1 -> 64-col strip

    wmma::fragment<wmma::accumulator, 16, 16, 8, float> acc[2][4];
    #pragma unroll
    for (int mi = 0; mi < 2; mi++)
        #pragma unroll
        for (int ni = 0; ni < 4; ni++) wmma::fill_fragment(acc[mi][ni], 0.0f);

    // ---- async load of one BK-chunk into stage st ----
    auto load_chunk = [&](int kc, int st) {
        const int k0 = kc * BK;
        float* a_base = As + st * A_STAGE;
        float* b_base = Bs + st * B_STAGE;
        // A: 128 rows x 32 floats = 1024 float4, 4 per thread
        #pragma unroll
        for (int i = 0; i < 4; i++) {
            int idx = i * 256 + tid;
            int r = idx >> 3, c = idx & 7;
            int gr = m0 + r;
            const float* src = A + (size_t)(gr < M ? gr : (M - 1)) * DDIM + k0 + c * 4;
            uint32_t dst;
            asm("{ .reg .u64 t; cvta.to.shared.u64 t, %1; cvt.u32.u64 %0, t; }"
                : "=r"(dst) : "l"(a_base + r * LDA + c * 4));
            int sz = (gr < M) ? 16 : 0;
            asm volatile("cp.async.cg.shared.global [%0], [%1], 16, %2;"
                         :: "r"(dst), "l"(src), "r"(sz));
        }
        // B: 32 rows x 128 floats = 1024 float4, 4 per thread
        #pragma unroll
        for (int i = 0; i < 4; i++) {
            int idx = i * 256 + tid;
            int r = idx >> 5, c = idx & 31;
            const float* src = Bsrc + (size_t)(k0 + r) * DDIM + ncol0 + c * 4;
            uint32_t dst;
            asm("{ .reg .u64 t; cvta.to.shared.u64 t, %1; cvt.u32.u64 %0, t; }"
                : "=r"(dst) : "l"(b_base + r * LDB + c * 4));
            asm volatile("cp.async.cg.shared.global [%0], [%1], 16;"
                         :: "r"(dst), "l"(src));
        }
        asm volatile("cp.async.commit_group;" ::: "memory");
    };

    load_chunk(0, 0);

    #pragma unroll 1
    for (int kc = 0; kc < CHUNKS; kc++) {
        const int st = kc & 1;
        if (kc + 1 < CHUNKS) {
            load_chunk(kc + 1, st ^ 1);
            asm volatile("cp.async.wait_group 1;" ::: "memory");
        } else {
            asm volatile("cp.async.wait_group 0;" ::: "memory");
        }
        __syncthreads();

        const float* a_base = As + st * A_STAGE;
        const float* b_base = Bs + st * B_STAGE;

        #pragma unroll
        for (int ks = 0; ks < BK / 8; ks++) {
            wmma::fragment<wmma::matrix_a, 16, 16, 8, wmma::precision::tf32, wmma::row_major> af[2];
            wmma::fragment<wmma::matrix_b, 16, 16, 8, wmma::precision::tf32, wmma::row_major> bf[4];
            #pragma unroll
            for (int mi = 0; mi < 2; mi++) {
                wmma::load_matrix_sync(af[mi],
                    a_base + (warp_m * 32 + mi * 16) * LDA + ks * 8, LDA);
                #pragma unroll
                for (int e = 0; e < af[mi].num_elements; e++)
                    af[mi].x[e] = wmma::__float_to_tf32(af[mi].x[e]);
            }
            #pragma unroll
            for (int ni = 0; ni < 4; ni++) {
                wmma::load_matrix_sync(bf[ni],
                    b_base + (ks * 8) * LDB + warp_n * 64 + ni * 16, LDB);
                #pragma unroll
                for (int e = 0; e < bf[ni].num_elements; e++)
                    bf[ni].x[e] = wmma::__float_to_tf32(bf[ni].x[e]);
            }
            #pragma unroll
            for (int mi = 0; mi < 2; mi++)
                #pragma unroll
                for (int ni = 0; ni < 4; ni++)
                    wmma::mma_sync(acc[mi][ni], af[mi], bf[ni], acc[mi][ni]);
        }
        __syncthreads();
    }

    // ---- epilogue ----
    if (m0 + MT <= M) {
        // fast path: direct fragment stores
        #pragma unroll
        for (int mi = 0; mi < 2; mi++)
            #pragma unroll
            for (int ni = 0; ni < 4; ni++) {
                int r = m0 + warp_m * 32 + mi * 16;
                int c = ncol0 + warp_n * 64 + ni * 16;
                wmma::store_matrix_sync(outbase + (size_t)r * DDIM + c,
                                        acc[mi][ni], DDIM, wmma::mem_row_major);
            }
    } else {
        // ragged M edge: stage through shared, guarded writes
        float* sC = smem;   // 128x128 floats = 64KB <= 70656B smem
        #pragma unroll
        for (int mi = 0; mi < 2; mi++)
            #pragma unroll
            for (int ni = 0; ni < 4; ni++) {
                int r = warp_m * 32 + mi * 16;
                int c = warp_n * 64 + ni * 16;
                wmma::store_matrix_sync(sC + r * NT + c, acc[mi][ni], NT,
                                        wmma::mem_row_major);
            }
        __syncthreads();
        #pragma unroll
        for (int i = 0; i < 16; i++) {
            int idx = i * 256 + tid;
            int r = idx >> 5, c = idx & 31;
            if (m0 + r < M) {
                float4 v = *(const float4*)(sC + r * NT + c * 4);
                *(float4*)(outbase + (size_t)(m0 + r) * DDIM + ncol0 + c * 4) = v;
            }
        }
    }
}

// ---------------------------------------------------------------------------
// Edge scatter: O[dst] += dis[src]*w*dis[dst] * H[src] (red.global.add.v4)
// ---------------------------------------------------------------------------
__global__ void scatter_edges_kernel(const int* __restrict__ src,
                                     const int* __restrict__ dst,
                                     const float* __restrict__ w,
                                     float* __restrict__ O)
{
    int e = blockIdx.x;
    int s = src[e];
    int d = dst[e];
    float coef = g_dis[s] * w[e] * g_dis[d];

    const float4* h = (const float4*)(g_H + (size_t)s * DDIM);
    float* o = O + (size_t)d * DDIM;

    int c = threadIdx.x;  // 0..127
    float4 v = h[c];
    asm volatile("red.global.add.v4.f32 [%0], {%1, %2, %3, %4};"
                 :: "l"(o + c * 4),
                    "f"(coef * v.x), "f"(coef * v.y), "f"(coef * v.z), "f"(coef * v.w)
                 : "memory");
}

// ---------------------------------------------------------------------------
// Finalize: O = leaky(O + FILL*dis^2 * H)
// ---------------------------------------------------------------------------
__device__ __forceinline__ float leaky(float v) { return v >= 0.0f ? v : NEG_SLOPE * v; }

__global__ void finalize_kernel(float* __restrict__ O) {
    size_t i = (size_t)blockIdx.x * blockDim.x + threadIdx.x;
    const size_t total = (size_t)NNODES * (DDIM / 4);
    if (i >= total) return;
    int n = (int)(i >> 7);
    float dn = g_dis[n];
    float sc = FILL * dn * dn;

    float4 h = ((const float4*)g_H)[i];
    float4 o = ((float4*)O)[i];
    o.x = leaky(o.x + sc * h.x);
    o.y = leaky(o.y + sc * h.y);
    o.z = leaky(o.z + sc * h.z);
    o.w = leaky(o.w + sc * h.w);
    ((float4*)O)[i] = o;
}

// ---------------------------------------------------------------------------
// Launch
// ---------------------------------------------------------------------------
extern "C" void kernel_launch(void* const* d_in, const int* in_sizes, int n_in,
                              void* d_out, int out_size)
{
    const float* x0   = (const float*)d_in[0];
    const float* x1   = (const float*)d_in[1];
    const float* x2   = (const float*)d_in[2];
    const int*   adj  = (const int*)d_in[3];
    const float* w    = (const float*)d_in[4];
    const float* Wmat = (const float*)d_in[5];
    const float* Wres = (const float*)d_in[6];
    float* out = (float*)d_out;

    const int* src = adj;
    const int* dst = adj + NEDGES;

    float* Hptr = nullptr;
    cudaGetSymbolAddress((void**)&Hptr, g_H);

    const int smem_bytes = SMEM_FLOATS * sizeof(float);   // 70656
    cudaFuncSetAttribute(gemm_tf32_wmma_kernel,
                         cudaFuncAttributeMaxDynamicSharedMemorySize, smem_bytes);

    // Norm precompute (shared across the 3 convs)
    init_deg_kernel<<<(NNODES + 255) / 256, 256>>>();
    accum_deg_kernel<<<(NEDGES + 255) / 256, 256>>>(dst, w);
    calc_dis_kernel<<<(NNODES + 255) / 256, 256>>>();

    dim3 gemm_grid(8, (NNODES + MT - 1) / MT);   // (8, 391)
    const size_t slice = (size_t)NNODES * DDIM;
    const int fin_blocks = (int)((slice / 4 + 255) / 256);
    const float* xs[3] = {x0, x1, x2};

    for (int t = 0; t < 3; t++) {
        float* O = out + (size_t)t * slice;
        // [H | O] = X @ [W | Wres]   (fused, tensor cores)
        gemm_tf32_wmma_kernel<<<gemm_grid, 256, smem_bytes>>>(
            xs[t], Wmat, Wres, Hptr, O, NNODES);
        // O += scatter(norm * H[src])
        scatter_edges_kernel<<<NEDGES, 128>>>(src, dst, w, O);
        // O = leaky(O + self_loop_norm * H)
        finalize_kernel<<<fin_blocks, 256>>>(O);
    }
}

// round 4
// speedup vs baseline: 1.7995x; 1.3371x over previous
#include <cuda_runtime.h>
#include <mma.h>
#include <cstdint>

using namespace nvcuda;

#define NNODES 50000
#define NEDGES 400000
#define DDIM   512
#define NCAT   1024
#define NEG_SLOPE 0.01f
#define FILL 2.0f

// ---------------------------------------------------------------------------
// Device scratch (static: no allocations allowed)
// ---------------------------------------------------------------------------
__device__ float g_Xr[(size_t)3 * NNODES * DDIM];  // tf32-rounded inputs (307MB)
__device__ float g_B[(size_t)DDIM * NCAT];         // tf32-rounded [W | Wres] (2MB)
__device__ float g_H[(size_t)NNODES * DDIM];       // H = X @ W (102.4MB)
__device__ float g_deg[NNODES];
__device__ float g_dis[NNODES];
__device__ int   g_cnt[NNODES];                    // in-degree counts / fill cursor
__device__ int   g_off[NNODES + 1];                // CSR offsets (by dst)
__device__ int   g_bsum[128];                      // scan block sums
__device__ int   g_srcs[NEDGES];                   // src node per CSR slot
__device__ float g_coef[NEDGES];                   // dis[s]*w*dis[d] per CSR slot

__device__ __forceinline__ uint32_t f2tf32(float f) {
    uint32_t r;
    asm("cvt.rna.tf32.f32 %0, %1;" : "=r"(r) : "f"(f));
    return r;
}

// ---------------------------------------------------------------------------
// Pre-rounding
// ---------------------------------------------------------------------------
__global__ void round_x_kernel(const float* __restrict__ x, float* __restrict__ dst, int n4) {
    int i = blockIdx.x * blockDim.x + threadIdx.x;
    if (i >= n4) return;
    float4 v = ((const float4*)x)[i];
    float4 o;
    o.x = __uint_as_float(f2tf32(v.x));
    o.y = __uint_as_float(f2tf32(v.y));
    o.z = __uint_as_float(f2tf32(v.z));
    o.w = __uint_as_float(f2tf32(v.w));
    ((float4*)dst)[i] = o;
}

__global__ void round_b_kernel(const float* __restrict__ W, const float* __restrict__ Wres) {
    int i = blockIdx.x * blockDim.x + threadIdx.x;   // over 512*1024
    if (i >= DDIM * NCAT) return;
    int k = i >> 10, n = i & 1023;
    float v = (n < DDIM) ? W[(size_t)k * DDIM + n] : Wres[(size_t)k * DDIM + (n - DDIM)];
    g_B[i] = __uint_as_float(f2tf32(v));
}

// ---------------------------------------------------------------------------
// Degree / norm / CSR build
// ---------------------------------------------------------------------------
__global__ void init_kernel() {
    int n = blockIdx.x * blockDim.x + threadIdx.x;
    if (n < NNODES) { g_deg[n] = FILL; g_cnt[n] = 0; }
}
__global__ void accum_kernel(const int* __restrict__ dst, const float* __restrict__ w) {
    int e = blockIdx.x * blockDim.x + threadIdx.x;
    if (e < NEDGES) {
        int d = dst[e];
        atomicAdd(&g_deg[d], w[e]);
        atomicAdd(&g_cnt[d], 1);
    }
}
__global__ void calc_dis_kernel() {
    int n = blockIdx.x * blockDim.x + threadIdx.x;
    if (n < NNODES) {
        float d = g_deg[n];
        g_dis[n] = (d > 0.0f) ? rsqrtf(d) : 0.0f;
    }
}

#define SCAN_BS 512
#define SCAN_NB ((NNODES + SCAN_BS - 1) / SCAN_BS)   // 98

__global__ void scan1_kernel() {   // per-block exclusive scan of g_cnt
    __shared__ int s[SCAN_BS];
    int tid = threadIdx.x;
    int i = blockIdx.x * SCAN_BS + tid;
    int val = (i < NNODES) ? g_cnt[i] : 0;
    s[tid] = val;
    __syncthreads();
    #pragma unroll
    for (int o = 1; o < SCAN_BS; o <<= 1) {
        int t = (tid >= o) ? s[tid - o] : 0;
        __syncthreads();
        s[tid] += t;
        __syncthreads();
    }
    int incl = s[tid];
    if (i < NNODES) g_off[i] = incl - val;
    if (tid == SCAN_BS - 1) g_bsum[blockIdx.x] = incl;
}
__global__ void scan2_kernel() {   // scan of 98 block sums (1 thread)
    if (threadIdx.x == 0) {
        int run = 0;
        for (int b = 0; b < SCAN_NB; b++) { int t = g_bsum[b]; g_bsum[b] = run; run += t; }
    }
}
__global__ void scan3_kernel() {   // add block offsets, reset cursor
    int i = blockIdx.x * blockDim.x + threadIdx.x;
    if (i < NNODES) { g_off[i] += g_bsum[i >> 9]; g_cnt[i] = 0; }
    if (i == 0) g_off[NNODES] = NEDGES;
}
__global__ void fill_kernel(const int* __restrict__ src, const int* __restrict__ dst,
                            const float* __restrict__ w) {
    int e = blockIdx.x * blockDim.x + threadIdx.x;
    if (e >= NEDGES) return;
    int s = src[e], d = dst[e];
    int pos = atomicAdd(&g_cnt[d], 1);
    int slot = g_off[d] + pos;
    g_srcs[slot] = s;
    g_coef[slot] = g_dis[s] * w[e] * g_dis[d];
}

// ---------------------------------------------------------------------------
// TF32 WMMA GEMM: C[M, 1024] = Xr[M,512] @ g_B. CTA 128x128, BK=32, 8 warps,
// warp tile 32x64. Inputs pre-rounded -> no cvt in mainloop. 2 CTAs/SM.
// ---------------------------------------------------------------------------
#define MT 128
#define NT 128
#define BK 32
#define LDA (BK + 4)
#define LDB (NT + 4)
#define A_STAGE (MT * LDA)
#define B_STAGE (BK * LDB)
#define SMEM_FLOATS (2 * (A_STAGE + B_STAGE))
#define CHUNKS (DDIM / BK)

__global__ __launch_bounds__(256, 2) void gemm_tf32_wmma_kernel(
    const float* __restrict__ A,     // rounded X slice [M, 512]
    float* __restrict__ H,           // [M, 512]
    float* __restrict__ O,           // [M, 512]
    int M)
{
    extern __shared__ float smem[];
    float* As = smem;
    float* Bs = smem + 2 * A_STAGE;

    const int tid = threadIdx.x;
    const int wid = tid >> 5;
    const int m0 = blockIdx.y * MT;
    const int bx = blockIdx.x;                // 0..7
    const int ncol0 = bx * NT;                // 0..896 within [H|O] concat

    const int warp_m = wid & 3;
    const int warp_n = wid >> 2;

    wmma::fragment<wmma::accumulator, 16, 16, 8, float> acc[2][4];
    #pragma unroll
    for (int mi = 0; mi < 2; mi++)
        #pragma unroll
        for (int ni = 0; ni < 4; ni++) wmma::fill_fragment(acc[mi][ni], 0.0f);

    auto load_chunk = [&](int kc, int st) {
        const int k0 = kc * BK;
        float* a_base = As + st * A_STAGE;
        float* b_base = Bs + st * B_STAGE;
        #pragma unroll
        for (int i = 0; i < 4; i++) {
            int idx = i * 256 + tid;
            int r = idx >> 3, c = idx & 7;
            int gr = m0 + r;
            const float* src = A + (size_t)(gr < M ? gr : (M - 1)) * DDIM + k0 + c * 4;
            uint32_t dst;
            asm("{ .reg .u64 t; cvta.to.shared.u64 t, %1; cvt.u32.u64 %0, t; }"
                : "=r"(dst) : "l"(a_base + r * LDA + c * 4));
            int sz = (gr < M) ? 16 : 0;
            asm volatile("cp.async.cg.shared.global [%0], [%1], 16, %2;"
                         :: "r"(dst), "l"(src), "r"(sz));
        }
        #pragma unroll
        for (int i = 0; i < 4; i++) {
            int idx = i * 256 + tid;
            int r = idx >> 5, c = idx & 31;
            const float* src = g_B + (size_t)(k0 + r) * NCAT + ncol0 + c * 4;
            uint32_t dst;
            asm("{ .reg .u64 t; cvta.to.shared.u64 t, %1; cvt.u32.u64 %0, t; }"
                : "=r"(dst) : "l"(b_base + r * LDB + c * 4));
            asm volatile("cp.async.cg.shared.global [%0], [%1], 16;"
                         :: "r"(dst), "l"(src));
        }
        asm volatile("cp.async.commit_group;" ::: "memory");
    };

    load_chunk(0, 0);

    #pragma unroll 1
    for (int kc = 0; kc < CHUNKS; kc++) {
        const int st = kc & 1;
        if (kc + 1 < CHUNKS) {
            load_chunk(kc + 1, st ^ 1);
            asm volatile("cp.async.wait_group 1;" ::: "memory");
        } else {
            asm volatile("cp.async.wait_group 0;" ::: "memory");
        }
        __syncthreads();

        const float* a_base = As + st * A_STAGE;
        const float* b_base = Bs + st * B_STAGE;

        #pragma unroll
        for (int ks = 0; ks < BK / 8; ks++) {
            wmma::fragment<wmma::matrix_a, 16, 16, 8, wmma::precision::tf32, wmma::row_major> af[2];
            wmma::fragment<wmma::matrix_b, 16, 16, 8, wmma::precision::tf32, wmma::row_major> bf[4];
            #pragma unroll
            for (int mi = 0; mi < 2; mi++)
                wmma::load_matrix_sync(af[mi],
                    a_base + (warp_m * 32 + mi * 16) * LDA + ks * 8, LDA);
            #pragma unroll
            for (int ni = 0; ni < 4; ni++)
                wmma::load_matrix_sync(bf[ni],
                    b_base + (ks * 8) * LDB + warp_n * 64 + ni * 16, LDB);
            #pragma unroll
            for (int mi = 0; mi < 2; mi++)
                #pragma unroll
                for (int ni = 0; ni < 4; ni++)
                    wmma::mma_sync(acc[mi][ni], af[mi], bf[ni], acc[mi][ni]);
        }
        __syncthreads();
    }

    float* outbase = (ncol0 < DDIM) ? H : O;
    const int oc0 = ncol0 & (DDIM - 1);

    if (m0 + MT <= M) {
        #pragma unroll
        for (int mi = 0; mi < 2; mi++)
            #pragma unroll
            for (int ni = 0; ni < 4; ni++) {
                int r = m0 + warp_m * 32 + mi * 16;
                int c = oc0 + warp_n * 64 + ni * 16;
                wmma::store_matrix_sync(outbase + (size_t)r * DDIM + c,
                                        acc[mi][ni], DDIM, wmma::mem_row_major);
            }
    } else {
        float* sC = smem;
        #pragma unroll
        for (int mi = 0; mi < 2; mi++)
            #pragma unroll
            for (int ni = 0; ni < 4; ni++) {
                int r = warp_m * 32 + mi * 16;
                int c = warp_n * 64 + ni * 16;
                wmma::store_matrix_sync(sC + r * NT + c, acc[mi][ni], NT,
                                        wmma::mem_row_major);
            }
        __syncthreads();
        #pragma unroll
        for (int i = 0; i < 16; i++) {
            int idx = i * 256 + tid;
            int r = idx >> 5, c = idx & 31;
            if (m0 + r < M) {
                float4 v = *(const float4*)(sC + r * NT + c * 4);
                *(float4*)(outbase + (size_t)(m0 + r) * DDIM + oc0 + c * 4) = v;
            }
        }
    }
}

// ---------------------------------------------------------------------------
// Fused gather + self-loop + residual + leaky relu. One block per node.
// O on entry holds X @ W_res; on exit holds the final conv output.
// ---------------------------------------------------------------------------
__global__ __launch_bounds__(128) void gather_finalize_kernel(float* __restrict__ O) {
    const int n = blockIdx.x;
    const int c = threadIdx.x;              // float4 column index 0..127

    const float dn = g_dis[n];
    const float sc = FILL * dn * dn;

    float4 h = ((const float4*)(g_H + (size_t)n * DDIM))[c];
    float ax = sc * h.x, ay = sc * h.y, az = sc * h.z, aw = sc * h.w;

    const int beg = g_off[n], end = g_off[n + 1];
    for (int j = beg; j < end; j++) {
        int s = g_srcs[j];
        float cf = g_coef[j];
        float4 v = ((const float4*)(g_H + (size_t)s * DDIM))[c];
        ax = fmaf(cf, v.x, ax);
        ay = fmaf(cf, v.y, ay);
        az = fmaf(cf, v.z, az);
        aw = fmaf(cf, v.w, aw);
    }

    float4* op = (float4*)(O + (size_t)n * DDIM) + c;
    float4 o = *op;
    o.x = o.x + ax; o.x = o.x >= 0.f ? o.x : NEG_SLOPE * o.x;
    o.y = o.y + ay; o.y = o.y >= 0.f ? o.y : NEG_SLOPE * o.y;
    o.z = o.z + az; o.z = o.z >= 0.f ? o.z : NEG_SLOPE * o.z;
    o.w = o.w + aw; o.w = o.w >= 0.f ? o.w : NEG_SLOPE * o.w;
    *op = o;
}

// ---------------------------------------------------------------------------
// Launch
// ---------------------------------------------------------------------------
extern "C" void kernel_launch(void* const* d_in, const int* in_sizes, int n_in,
                              void* d_out, int out_size)
{
    const float* x0   = (const float*)d_in[0];
    const float* x1   = (const float*)d_in[1];
    const float* x2   = (const float*)d_in[2];
    const int*   adj  = (const int*)d_in[3];
    const float* w    = (const float*)d_in[4];
    const float* Wmat = (const float*)d_in[5];
    const float* Wres = (const float*)d_in[6];
    float* out = (float*)d_out;

    const int* src = adj;
    const int* dst = adj + NEDGES;

    float *Hptr = nullptr, *Xrptr = nullptr;
    cudaGetSymbolAddress((void**)&Hptr, g_H);
    cudaGetSymbolAddress((void**)&Xrptr, g_Xr);

    const int smem_bytes = SMEM_FLOATS * sizeof(float);
    cudaFuncSetAttribute(gemm_tf32_wmma_kernel,
                         cudaFuncAttributeMaxDynamicSharedMemorySize, smem_bytes);

    const size_t slice = (size_t)NNODES * DDIM;
    const int n4 = (int)(slice / 4);
    const float* xs[3] = {x0, x1, x2};

    // Pre-round inputs/weights to tf32
    for (int t = 0; t < 3; t++)
        round_x_kernel<<<(n4 + 255) / 256, 256>>>(xs[t], Xrptr + (size_t)t * slice, n4);
    round_b_kernel<<<(DDIM * NCAT + 255) / 256, 256>>>(Wmat, Wres);

    // Norm + CSR build (shared across the 3 convs)
    init_kernel<<<(NNODES + 255) / 256, 256>>>();
    accum_kernel<<<(NEDGES + 255) / 256, 256>>>(dst, w);
    calc_dis_kernel<<<(NNODES + 255) / 256, 256>>>();
    scan1_kernel<<<SCAN_NB, SCAN_BS>>>();
    scan2_kernel<<<1, 32>>>();
    scan3_kernel<<<(NNODES + 255) / 256, 256>>>();
    fill_kernel<<<(NEDGES + 255) / 256, 256>>>(src, dst, w);

    dim3 gemm_grid(8, (NNODES + MT - 1) / MT);   // (8, 391)

    for (int t = 0; t < 3; t++) {
        float* O = out + (size_t)t * slice;
        gemm_tf32_wmma_kernel<<<gemm_grid, 256, smem_bytes>>>(
            Xrptr + (size_t)t * slice, Hptr, O, NNODES);
        gather_finalize_kernel<<<NNODES, 128>>>(O);
    }
}

// round 5
// speedup vs baseline: 1.9478x; 1.0824x over previous
#include <cuda_runtime.h>
#include <mma.h>
#include <cstdint>

using namespace nvcuda;

#define NNODES 50000
#define NEDGES 400000
#define DDIM   512
#define NCAT   1024
#define NEG_SLOPE 0.01f
#define FILL 2.0f

// ---------------------------------------------------------------------------
// Device scratch (static: no allocations allowed)
// ---------------------------------------------------------------------------
__device__ float g_B[(size_t)DDIM * NCAT];           // tf32-rounded [W | Wres]
__device__ float g_H[(size_t)3 * NNODES * DDIM];     // H_t = X_t @ W (3 slices)
__device__ float g_deg[NNODES];
__device__ float g_dis[NNODES];
__device__ int   g_cnt[NNODES];
__device__ int   g_off[NNODES + 1];
__device__ int   g_bsum[128];
__device__ int   g_srcs[NEDGES];
__device__ float g_coef[NEDGES];

__device__ __forceinline__ uint32_t f2tf32(float f) {
    uint32_t r;
    asm("cvt.rna.tf32.f32 %0, %1;" : "=r"(r) : "f"(f));
    return r;
}

// ---------------------------------------------------------------------------
// Weight pre-rounding (2 MB, one-shot)
// ---------------------------------------------------------------------------
__global__ void round_b_kernel(const float* __restrict__ W, const float* __restrict__ Wres) {
    int i = blockIdx.x * blockDim.x + threadIdx.x;
    if (i >= DDIM * NCAT) return;
    int k = i >> 10, n = i & 1023;
    float v = (n < DDIM) ? W[(size_t)k * DDIM + n] : Wres[(size_t)k * DDIM + (n - DDIM)];
    g_B[i] = __uint_as_float(f2tf32(v));
}

// ---------------------------------------------------------------------------
// Degree / norm / CSR build
// ---------------------------------------------------------------------------
__global__ void init_kernel() {
    int n = blockIdx.x * blockDim.x + threadIdx.x;
    if (n < NNODES) { g_deg[n] = FILL; g_cnt[n] = 0; }
}
__global__ void accum_kernel(const int* __restrict__ dst, const float* __restrict__ w) {
    int e = blockIdx.x * blockDim.x + threadIdx.x;
    if (e < NEDGES) {
        int d = dst[e];
        atomicAdd(&g_deg[d], w[e]);
        atomicAdd(&g_cnt[d], 1);
    }
}
__global__ void calc_dis_kernel() {
    int n = blockIdx.x * blockDim.x + threadIdx.x;
    if (n < NNODES) {
        float d = g_deg[n];
        g_dis[n] = (d > 0.0f) ? rsqrtf(d) : 0.0f;
    }
}

#define SCAN_BS 512
#define SCAN_NB ((NNODES + SCAN_BS - 1) / SCAN_BS)   // 98

__global__ void scan1_kernel() {
    __shared__ int s[SCAN_BS];
    int tid = threadIdx.x;
    int i = blockIdx.x * SCAN_BS + tid;
    int val = (i < NNODES) ? g_cnt[i] : 0;
    s[tid] = val;
    __syncthreads();
    #pragma unroll
    for (int o = 1; o < SCAN_BS; o <<= 1) {
        int t = (tid >= o) ? s[tid - o] : 0;
        __syncthreads();
        s[tid] += t;
        __syncthreads();
    }
    int incl = s[tid];
    if (i < NNODES) g_off[i] = incl - val;
    if (tid == SCAN_BS - 1) g_bsum[blockIdx.x] = incl;
}
__global__ void scan2_kernel() {
    if (threadIdx.x == 0) {
        int run = 0;
        for (int b = 0; b < SCAN_NB; b++) { int t = g_bsum[b]; g_bsum[b] = run; run += t; }
    }
}
__global__ void scan3_kernel() {
    int i = blockIdx.x * blockDim.x + threadIdx.x;
    if (i < NNODES) { g_off[i] += g_bsum[i >> 9]; g_cnt[i] = 0; }
    if (i == 0) g_off[NNODES] = NEDGES;
}
__global__ void fill_kernel(const int* __restrict__ src, const int* __restrict__ dst,
                            const float* __restrict__ w) {
    int e = blockIdx.x * blockDim.x + threadIdx.x;
    if (e >= NEDGES) return;
    int s = src[e], d = dst[e];
    int pos = atomicAdd(&g_cnt[d], 1);
    int slot = g_off[d] + pos;
    g_srcs[slot] = s;
    g_coef[slot] = g_dis[s] * w[e] * g_dis[d];
}

// ---------------------------------------------------------------------------
// TF32 WMMA GEMM, batched over the 3 inputs via grid.z.
// C_t[M, 1024] = X_t[M,512] @ g_B. CTA 128x128, BK=32, 8 warps (32x64 warp
// tile). B pre-rounded; A rounded per-fragment in registers (no pre-pass).
// ---------------------------------------------------------------------------
#define MT 128
#define NT 128
#define BK 32
#define LDA (BK + 4)
#define LDB (NT + 4)
#define A_STAGE (MT * LDA)
#define B_STAGE (BK * LDB)
#define SMEM_FLOATS (2 * (A_STAGE + B_STAGE))
#define CHUNKS (DDIM / BK)

__global__ __launch_bounds__(256, 2) void gemm_tf32_wmma_kernel(
    const float* __restrict__ X0,
    const float* __restrict__ X1,
    const float* __restrict__ X2,
    float* __restrict__ Hbase,       // [3, M, 512]
    float* __restrict__ Obase,       // [3, M, 512] (d_out)
    int M)
{
    extern __shared__ float smem[];
    float* As = smem;
    float* Bs = smem + 2 * A_STAGE;

    const int tid = threadIdx.x;
    const int wid = tid >> 5;
    const int m0 = blockIdx.y * MT;
    const int ncol0 = blockIdx.x * NT;        // within [H|O] concat
    const int t = blockIdx.z;

    const float* A = (t == 0) ? X0 : (t == 1) ? X1 : X2;
    const size_t slice = (size_t)M * DDIM;

    const int warp_m = wid & 3;
    const int warp_n = wid >> 2;

    wmma::fragment<wmma::accumulator, 16, 16, 8, float> acc[2][4];
    #pragma unroll
    for (int mi = 0; mi < 2; mi++)
        #pragma unroll
        for (int ni = 0; ni < 4; ni++) wmma::fill_fragment(acc[mi][ni], 0.0f);

    auto load_chunk = [&](int kc, int st) {
        const int k0 = kc * BK;
        float* a_base = As + st * A_STAGE;
        float* b_base = Bs + st * B_STAGE;
        #pragma unroll
        for (int i = 0; i < 4; i++) {
            int idx = i * 256 + tid;
            int r = idx >> 3, c = idx & 7;
            int gr = m0 + r;
            const float* src = A + (size_t)(gr < M ? gr : (M - 1)) * DDIM + k0 + c * 4;
            uint32_t dst;
            asm("{ .reg .u64 t; cvta.to.shared.u64 t, %1; cvt.u32.u64 %0, t; }"
                : "=r"(dst) : "l"(a_base + r * LDA + c * 4));
            int sz = (gr < M) ? 16 : 0;
            asm volatile("cp.async.cg.shared.global [%0], [%1], 16, %2;"
                         :: "r"(dst), "l"(src), "r"(sz));
        }
        #pragma unroll
        for (int i = 0; i < 4; i++) {
            int idx = i * 256 + tid;
            int r = idx >> 5, c = idx & 31;
            const float* src = g_B + (size_t)(k0 + r) * NCAT + ncol0 + c * 4;
            uint32_t dst;
            asm("{ .reg .u64 t; cvta.to.shared.u64 t, %1; cvt.u32.u64 %0, t; }"
                : "=r"(dst) : "l"(b_base + r * LDB + c * 4));
            asm volatile("cp.async.cg.shared.global [%0], [%1], 16;"
                         :: "r"(dst), "l"(src));
        }
        asm volatile("cp.async.commit_group;" ::: "memory");
    };

    load_chunk(0, 0);

    #pragma unroll 1
    for (int kc = 0; kc < CHUNKS; kc++) {
        const int st = kc & 1;
        if (kc + 1 < CHUNKS) {
            load_chunk(kc + 1, st ^ 1);
            asm volatile("cp.async.wait_group 1;" ::: "memory");
        } else {
            asm volatile("cp.async.wait_group 0;" ::: "memory");
        }
        __syncthreads();

        const float* a_base = As + st * A_STAGE;
        const float* b_base = Bs + st * B_STAGE;

        #pragma unroll
        for (int ks = 0; ks < BK / 8; ks++) {
            wmma::fragment<wmma::matrix_a, 16, 16, 8, wmma::precision::tf32, wmma::row_major> af[2];
            wmma::fragment<wmma::matrix_b, 16, 16, 8, wmma::precision::tf32, wmma::row_major> bf[4];
            #pragma unroll
            for (int mi = 0; mi < 2; mi++) {
                wmma::load_matrix_sync(af[mi],
                    a_base + (warp_m * 32 + mi * 16) * LDA + ks * 8, LDA);
                #pragma unroll
                for (int e = 0; e < af[mi].num_elements; e++)
                    af[mi].x[e] = __uint_as_float(f2tf32(af[mi].x[e]));
            }
            #pragma unroll
            for (int ni = 0; ni < 4; ni++)
                wmma::load_matrix_sync(bf[ni],
                    b_base + (ks * 8) * LDB + warp_n * 64 + ni * 16, LDB);
            #pragma unroll
            for (int mi = 0; mi < 2; mi++)
                #pragma unroll
                for (int ni = 0; ni < 4; ni++)
                    wmma::mma_sync(acc[mi][ni], af[mi], bf[ni], acc[mi][ni]);
        }
        __syncthreads();
    }

    float* outbase = ((ncol0 < DDIM) ? (Hbase + t * slice) : (Obase + t * slice));
    const int oc0 = ncol0 & (DDIM - 1);

    if (m0 + MT <= M) {
        #pragma unroll
        for (int mi = 0; mi < 2; mi++)
            #pragma unroll
            for (int ni = 0; ni < 4; ni++) {
                int r = m0 + warp_m * 32 + mi * 16;
                int c = oc0 + warp_n * 64 + ni * 16;
                wmma::store_matrix_sync(outbase + (size_t)r * DDIM + c,
                                        acc[mi][ni], DDIM, wmma::mem_row_major);
            }
    } else {
        float* sC = smem;
        #pragma unroll
        for (int mi = 0; mi < 2; mi++)
            #pragma unroll
            for (int ni = 0; ni < 4; ni++) {
                int r = warp_m * 32 + mi * 16;
                int c = warp_n * 64 + ni * 16;
                wmma::store_matrix_sync(sC + r * NT + c, acc[mi][ni], NT,
                                        wmma::mem_row_major);
            }
        __syncthreads();
        #pragma unroll
        for (int i = 0; i < 16; i++) {
            int idx = i * 256 + tid;
            int r = idx >> 5, c = idx & 31;
            if (m0 + r < M) {
                float4 v = *(const float4*)(sC + r * NT + c * 4);
                *(float4*)(outbase + (size_t)(m0 + r) * DDIM + oc0 + c * 4) = v;
            }
        }
    }
}

// ---------------------------------------------------------------------------
// Fused gather + self-loop + residual + leaky relu, batched over 3 convs.
// One block per (node, t). Edge loop unrolled x2 with dual accumulators.
// ---------------------------------------------------------------------------
__global__ __launch_bounds__(128) void gather_finalize_kernel(float* __restrict__ Obase) {
    const int n = blockIdx.x;
    const int t = blockIdx.y;
    const int c = threadIdx.x;              // float4 column index 0..127

    const size_t slice = (size_t)NNODES * DDIM;
    const float* Ht = g_H + t * slice;
    float* O = Obase + t * slice;

    const float dn = g_dis[n];
    const float sc = FILL * dn * dn;

    float4 h = __ldg(((const float4*)(Ht + (size_t)n * DDIM)) + c);
    float ax = sc * h.x, ay = sc * h.y, az = sc * h.z, aw = sc * h.w;
    float bx = 0.f, by = 0.f, bz = 0.f, bw = 0.f;

    const int beg = g_off[n], end = g_off[n + 1];
    int j = beg;
    for (; j + 1 < end; j += 2) {
        int s0 = g_srcs[j], s1 = g_srcs[j + 1];
        float c0 = g_coef[j], c1 = g_coef[j + 1];
        float4 v0 = __ldg(((const float4*)(Ht + (size_t)s0 * DDIM)) + c);
        float4 v1 = __ldg(((const float4*)(Ht + (size_t)s1 * DDIM)) + c);
        ax = fmaf(c0, v0.x, ax); ay = fmaf(c0, v0.y, ay);
        az = fmaf(c0, v0.z, az); aw = fmaf(c0, v0.w, aw);
        bx = fmaf(c1, v1.x, bx); by = fmaf(c1, v1.y, by);
        bz = fmaf(c1, v1.z, bz); bw = fmaf(c1, v1.w, bw);
    }
    if (j < end) {
        int s0 = g_srcs[j];
        float c0 = g_coef[j];
        float4 v0 = __ldg(((const float4*)(Ht + (size_t)s0 * DDIM)) + c);
        ax = fmaf(c0, v0.x, ax); ay = fmaf(c0, v0.y, ay);
        az = fmaf(c0, v0.z, az); aw = fmaf(c0, v0.w, aw);
    }
    ax += bx; ay += by; az += bz; aw += bw;

    float4* op = (float4*)(O + (size_t)n * DDIM) + c;
    float4 o = *op;
    o.x = o.x + ax; o.x = o.x >= 0.f ? o.x : NEG_SLOPE * o.x;
    o.y = o.y + ay; o.y = o.y >= 0.f ? o.y : NEG_SLOPE * o.y;
    o.z = o.z + az; o.z = o.z >= 0.f ? o.z : NEG_SLOPE * o.z;
    o.w = o.w + aw; o.w = o.w >= 0.f ? o.w : NEG_SLOPE * o.w;
    *op = o;
}

// ---------------------------------------------------------------------------
// Launch
// ---------------------------------------------------------------------------
extern "C" void kernel_launch(void* const* d_in, const int* in_sizes, int n_in,
                              void* d_out, int out_size)
{
    const float* x0   = (const float*)d_in[0];
    const float* x1   = (const float*)d_in[1];
    const float* x2   = (const float*)d_in[2];
    const int*   adj  = (const int*)d_in[3];
    const float* w    = (const float*)d_in[4];
    const float* Wmat = (const float*)d_in[5];
    const float* Wres = (const float*)d_in[6];
    float* out = (float*)d_out;

    const int* src = adj;
    const int* dst = adj + NEDGES;

    float* Hptr = nullptr;
    cudaGetSymbolAddress((void**)&Hptr, g_H);

    const int smem_bytes = SMEM_FLOATS * sizeof(float);
    cudaFuncSetAttribute(gemm_tf32_wmma_kernel,
                         cudaFuncAttributeMaxDynamicSharedMemorySize, smem_bytes);

    // Weight pre-round + norm/CSR build (independent of GEMM; cheap)
    round_b_kernel<<<(DDIM * NCAT + 255) / 256, 256>>>(Wmat, Wres);
    init_kernel<<<(NNODES + 255) / 256, 256>>>();
    accum_kernel<<<(NEDGES + 255) / 256, 256>>>(dst, w);
    calc_dis_kernel<<<(NNODES + 255) / 256, 256>>>();
    scan1_kernel<<<SCAN_NB, SCAN_BS>>>();
    scan2_kernel<<<1, 32>>>();
    scan3_kernel<<<(NNODES + 255) / 256, 256>>>();
    fill_kernel<<<(NEDGES + 255) / 256, 256>>>(src, dst, w);

    // One batched GEMM over all 3 inputs: [H_t | O_t] = X_t @ [W | Wres]
    dim3 gemm_grid(8, (NNODES + MT - 1) / MT, 3);
    gemm_tf32_wmma_kernel<<<gemm_grid, 256, smem_bytes>>>(
        x0, x1, x2, Hptr, out, NNODES);

    // One batched gather/finalize over all 3 convs
    dim3 gather_grid(NNODES, 3);
    gather_finalize_kernel<<<gather_grid, 128>>>(out);
}

// round 6
// speedup vs baseline: 4.7564x; 2.4419x over previous
#include <cuda_runtime.h>
#include <cuda_fp16.h>
#include <mma.h>
#include <cstdint>

using namespace nvcuda;

#define NNODES 50000
#define NEDGES 400000
#define DDIM   512
#define NCAT   1024
#define NEG_SLOPE 0.01f
#define FILL 2.0f

// ---------------------------------------------------------------------------
// Device scratch (static: no allocations allowed)
// ---------------------------------------------------------------------------
__device__ __half g_Xh[(size_t)3 * NNODES * DDIM];  // fp16 inputs (153.6MB)
__device__ __half g_Bh[(size_t)DDIM * NCAT];        // fp16 [W | Wres] (1MB)
__device__ float  g_H[(size_t)3 * NNODES * DDIM];   // H_t = X_t @ W (fp32)
__device__ float  g_deg[NNODES];
__device__ float  g_dis[NNODES];
__device__ int    g_cnt[NNODES];
__device__ int    g_off[NNODES + 1];
__device__ int    g_bsum[128];
__device__ int    g_srcs[NEDGES];
__device__ float  g_coef[NEDGES];

// ---------------------------------------------------------------------------
// fp32 -> fp16 conversion passes
// ---------------------------------------------------------------------------
__global__ void conv_x_kernel(const float* __restrict__ x0,
                              const float* __restrict__ x1,
                              const float* __restrict__ x2, int n4) {
    int i = blockIdx.x * blockDim.x + threadIdx.x;   // float4 index within slice
    if (i >= n4) return;
    int t = blockIdx.y;
    const float* x = (t == 0) ? x0 : (t == 1) ? x1 : x2;
    float4 v = ((const float4*)x)[i];
    __half2 lo = __floats2half2_rn(v.x, v.y);
    __half2 hi = __floats2half2_rn(v.z, v.w);
    __half2* dst = (__half2*)(g_Xh + (size_t)t * NNODES * DDIM) + 2 * i;
    dst[0] = lo;
    dst[1] = hi;
}

__global__ void conv_b_kernel(const float* __restrict__ W, const float* __restrict__ Wres) {
    int i = blockIdx.x * blockDim.x + threadIdx.x;
    if (i >= DDIM * NCAT) return;
    int k = i >> 10, n = i & 1023;
    float v = (n < DDIM) ? W[(size_t)k * DDIM + n] : Wres[(size_t)k * DDIM + (n - DDIM)];
    g_Bh[i] = __float2half_rn(v);
}

// ---------------------------------------------------------------------------
// Degree / norm / CSR build
// ---------------------------------------------------------------------------
__global__ void init_kernel() {
    int n = blockIdx.x * blockDim.x + threadIdx.x;
    if (n < NNODES) { g_deg[n] = FILL; g_cnt[n] = 0; }
}
__global__ void accum_kernel(const int* __restrict__ dst, const float* __restrict__ w) {
    int e = blockIdx.x * blockDim.x + threadIdx.x;
    if (e < NEDGES) {
        int d = dst[e];
        atomicAdd(&g_deg[d], w[e]);
        atomicAdd(&g_cnt[d], 1);
    }
}
__global__ void calc_dis_kernel() {
    int n = blockIdx.x * blockDim.x + threadIdx.x;
    if (n < NNODES) {
        float d = g_deg[n];
        g_dis[n] = (d > 0.0f) ? rsqrtf(d) : 0.0f;
    }
}

#define SCAN_BS 512
#define SCAN_NB ((NNODES + SCAN_BS - 1) / SCAN_BS)   // 98

__global__ void scan1_kernel() {
    __shared__ int s[SCAN_BS];
    int tid = threadIdx.x;
    int i = blockIdx.x * SCAN_BS + tid;
    int val = (i < NNODES) ? g_cnt[i] : 0;
    s[tid] = val;
    __syncthreads();
    #pragma unroll
    for (int o = 1; o < SCAN_BS; o <<= 1) {
        int t = (tid >= o) ? s[tid - o] : 0;
        __syncthreads();
        s[tid] += t;
        __syncthreads();
    }
    int incl = s[tid];
    if (i < NNODES) g_off[i] = incl - val;
    if (tid == SCAN_BS - 1) g_bsum[blockIdx.x] = incl;
}
__global__ void scan2_kernel() {
    if (threadIdx.x == 0) {
        int run = 0;
        for (int b = 0; b < SCAN_NB; b++) { int t = g_bsum[b]; g_bsum[b] = run; run += t; }
    }
}
__global__ void scan3_kernel() {
    int i = blockIdx.x * blockDim.x + threadIdx.x;
    if (i < NNODES) { g_off[i] += g_bsum[i >> 9]; g_cnt[i] = 0; }
    if (i == 0) g_off[NNODES] = NEDGES;
}
__global__ void fill_kernel(const int* __restrict__ src, const int* __restrict__ dst,
                            const float* __restrict__ w) {
    int e = blockIdx.x * blockDim.x + threadIdx.x;
    if (e >= NEDGES) return;
    int s = src[e], d = dst[e];
    int pos = atomicAdd(&g_cnt[d], 1);
    int slot = g_off[d] + pos;
    g_srcs[slot] = s;
    g_coef[slot] = g_dis[s] * w[e] * g_dis[d];
}

// ---------------------------------------------------------------------------
// FP16 WMMA GEMM (fp32 accumulate), batched over the 3 inputs via grid.z.
// C_t[M, 1024] = Xh_t[M,512] @ g_Bh. CTA 128x128, BK=32, 8 warps (32x64
// warp tile, 2x4 wmma m16n16k16). Double-buffered cp.async.
// ---------------------------------------------------------------------------
#define MT 128
#define NT 128
#define BK 32
#define LDA (BK + 8)       // halves; row stride 80B (16B-aligned)
#define LDB (NT + 8)       // halves; row stride 272B (16B-aligned)
#define A_STAGE (MT * LDA) // halves
#define B_STAGE (BK * LDB) // halves
#define SMEM_BYTES 65536   // >= 2*(A_STAGE+B_STAGE)*2 (37,888B) and 128x128 f32 staging
#define CHUNKS (DDIM / BK)

__global__ __launch_bounds__(256, 2) void gemm_fp16_wmma_kernel(
    float* __restrict__ Hbase,       // [3, M, 512]
    float* __restrict__ Obase,       // [3, M, 512] (d_out)
    int M)
{
    extern __shared__ char smem_raw[];
    __half* As = (__half*)smem_raw;
    __half* Bs = As + 2 * A_STAGE;

    const int tid = threadIdx.x;
    const int wid = tid >> 5;
    const int m0 = blockIdx.y * MT;
    const int ncol0 = blockIdx.x * NT;
    const int t = blockIdx.z;

    const __half* A = g_Xh + (size_t)t * M * DDIM;
    const size_t slice = (size_t)M * DDIM;

    const int warp_m = wid & 3;
    const int warp_n = wid >> 2;

    wmma::fragment<wmma::accumulator, 16, 16, 16, float> acc[2][4];
    #pragma unroll
    for (int mi = 0; mi < 2; mi++)
        #pragma unroll
        for (int ni = 0; ni < 4; ni++) wmma::fill_fragment(acc[mi][ni], 0.0f);

    auto load_chunk = [&](int kc, int st) {
        const int k0 = kc * BK;
        __half* a_base = As + st * A_STAGE;
        __half* b_base = Bs + st * B_STAGE;
        // A: 128 rows x 32 halves = 512 x 16B chunks, 2 per thread
        #pragma unroll
        for (int i = 0; i < 2; i++) {
            int idx = i * 256 + tid;
            int r = idx >> 2, c = idx & 3;
            int gr = m0 + r;
            const __half* src = A + (size_t)(gr < M ? gr : (M - 1)) * DDIM + k0 + c * 8;
            uint32_t dst;
            asm("{ .reg .u64 t; cvta.to.shared.u64 t, %1; cvt.u32.u64 %0, t; }"
                : "=r"(dst) : "l"(a_base + r * LDA + c * 8));
            int sz = (gr < M) ? 16 : 0;
            asm volatile("cp.async.cg.shared.global [%0], [%1], 16, %2;"
                         :: "r"(dst), "l"(src), "r"(sz));
        }
        // B: 32 rows x 128 halves = 512 x 16B chunks, 2 per thread
        #pragma unroll
        for (int i = 0; i < 2; i++) {
            int idx = i * 256 + tid;
            int r = idx >> 4, c = idx & 15;
            const __half* src = g_Bh + (size_t)(k0 + r) * NCAT + ncol0 + c * 8;
            uint32_t dst;
            asm("{ .reg .u64 t; cvta.to.shared.u64 t, %1; cvt.u32.u64 %0, t; }"
                : "=r"(dst) : "l"(b_base + r * LDB + c * 8));
            asm volatile("cp.async.cg.shared.global [%0], [%1], 16;"
                         :: "r"(dst), "l"(src));
        }
        asm volatile("cp.async.commit_group;" ::: "memory");
    };

    load_chunk(0, 0);

    #pragma unroll 1
    for (int kc = 0; kc < CHUNKS; kc++) {
        const int st = kc & 1;
        if (kc + 1 < CHUNKS) {
            load_chunk(kc + 1, st ^ 1);
            asm volatile("cp.async.wait_group 1;" ::: "memory");
        } else {
            asm volatile("cp.async.wait_group 0;" ::: "memory");
        }
        __syncthreads();

        const __half* a_base = As + st * A_STAGE;
        const __half* b_base = Bs + st * B_STAGE;

        #pragma unroll
        for (int ks = 0; ks < BK / 16; ks++) {
            wmma::fragment<wmma::matrix_a, 16, 16, 16, __half, wmma::row_major> af[2];
            wmma::fragment<wmma::matrix_b, 16, 16, 16, __half, wmma::row_major> bf[4];
            #pragma unroll
            for (int mi = 0; mi < 2; mi++)
                wmma::load_matrix_sync(af[mi],
                    a_base + (warp_m * 32 + mi * 16) * LDA + ks * 16, LDA);
            #pragma unroll
            for (int ni = 0; ni < 4; ni++)
                wmma::load_matrix_sync(bf[ni],
                    b_base + (ks * 16) * LDB + warp_n * 64 + ni * 16, LDB);
            #pragma unroll
            for (int mi = 0; mi < 2; mi++)
                #pragma unroll
                for (int ni = 0; ni < 4; ni++)
                    wmma::mma_sync(acc[mi][ni], af[mi], bf[ni], acc[mi][ni]);
        }
        __syncthreads();
    }

    float* outbase = ((ncol0 < DDIM) ? (Hbase + t * slice) : (Obase + t * slice));
    const int oc0 = ncol0 & (DDIM - 1);

    if (m0 + MT <= M) {
        #pragma unroll
        for (int mi = 0; mi < 2; mi++)
            #pragma unroll
            for (int ni = 0; ni < 4; ni++) {
                int r = m0 + warp_m * 32 + mi * 16;
                int c = oc0 + warp_n * 64 + ni * 16;
                wmma::store_matrix_sync(outbase + (size_t)r * DDIM + c,
                                        acc[mi][ni], DDIM, wmma::mem_row_major);
            }
    } else {
        float* sC = (float*)smem_raw;   // 128x128 f32 = 64KB staging
        #pragma unroll
        for (int mi = 0; mi < 2; mi++)
            #pragma unroll
            for (int ni = 0; ni < 4; ni++) {
                int r = warp_m * 32 + mi * 16;
                int c = warp_n * 64 + ni * 16;
                wmma::store_matrix_sync(sC + r * NT + c, acc[mi][ni], NT,
                                        wmma::mem_row_major);
            }
        __syncthreads();
        #pragma unroll
        for (int i = 0; i < 16; i++) {
            int idx = i * 256 + tid;
            int r = idx >> 5, c = idx & 31;
            if (m0 + r < M) {
                float4 v = *(const float4*)(sC + r * NT + c * 4);
                *(float4*)(outbase + (size_t)(m0 + r) * DDIM + oc0 + c * 4) = v;
            }
        }
    }
}

// ---------------------------------------------------------------------------
// Fused gather + self-loop + residual + leaky relu, batched over 3 convs.
// One block per (node, t). Edge loop unrolled x2 with dual accumulators.
// ---------------------------------------------------------------------------
__global__ __launch_bounds__(128) void gather_finalize_kernel(float* __restrict__ Obase) {
    const int n = blockIdx.x;
    const int t = blockIdx.y;
    const int c = threadIdx.x;              // float4 column index 0..127

    const size_t slice = (size_t)NNODES * DDIM;
    const float* Ht = g_H + t * slice;
    float* O = Obase + t * slice;

    const float dn = g_dis[n];
    const float sc = FILL * dn * dn;

    float4 h = __ldg(((const float4*)(Ht + (size_t)n * DDIM)) + c);
    float ax = sc * h.x, ay = sc * h.y, az = sc * h.z, aw = sc * h.w;
    float bx = 0.f, by = 0.f, bz = 0.f, bw = 0.f;

    const int beg = g_off[n], end = g_off[n + 1];
    int j = beg;
    for (; j + 1 < end; j += 2) {
        int s0 = g_srcs[j], s1 = g_srcs[j + 1];
        float c0 = g_coef[j], c1 = g_coef[j + 1];
        float4 v0 = __ldg(((const float4*)(Ht + (size_t)s0 * DDIM)) + c);
        float4 v1 = __ldg(((const float4*)(Ht + (size_t)s1 * DDIM)) + c);
        ax = fmaf(c0, v0.x, ax); ay = fmaf(c0, v0.y, ay);
        az = fmaf(c0, v0.z, az); aw = fmaf(c0, v0.w, aw);
        bx = fmaf(c1, v1.x, bx); by = fmaf(c1, v1.y, by);
        bz = fmaf(c1, v1.z, bz); bw = fmaf(c1, v1.w, bw);
    }
    if (j < end) {
        int s0 = g_srcs[j];
        float c0 = g_coef[j];
        float4 v0 = __ldg(((const float4*)(Ht + (size_t)s0 * DDIM)) + c);
        ax = fmaf(c0, v0.x, ax); ay = fmaf(c0, v0.y, ay);
        az = fmaf(c0, v0.z, az); aw = fmaf(c0, v0.w, aw);
    }
    ax += bx; ay += by; az += bz; aw += bw;

    float4* op = (float4*)(O + (size_t)n * DDIM) + c;
    float4 o = *op;
    o.x = o.x + ax; o.x = o.x >= 0.f ? o.x : NEG_SLOPE * o.x;
    o.y = o.y + ay; o.y = o.y >= 0.f ? o.y : NEG_SLOPE * o.y;
    o.z = o.z + az; o.z = o.z >= 0.f ? o.z : NEG_SLOPE * o.z;
    o.w = o.w + aw; o.w = o.w >= 0.f ? o.w : NEG_SLOPE * o.w;
    *op = o;
}

// ---------------------------------------------------------------------------
// Launch
// ---------------------------------------------------------------------------
extern "C" void kernel_launch(void* const* d_in, const int* in_sizes, int n_in,
                              void* d_out, int out_size)
{
    const float* x0   = (const float*)d_in[0];
    const float* x1   = (const float*)d_in[1];
    const float* x2   = (const float*)d_in[2];
    const int*   adj  = (const int*)d_in[3];
    const float* w    = (const float*)d_in[4];
    const float* Wmat = (const float*)d_in[5];
    const float* Wres = (const float*)d_in[6];
    float* out = (float*)d_out;

    const int* src = adj;
    const int* dst = adj + NEDGES;

    float* Hptr = nullptr;
    cudaGetSymbolAddress((void**)&Hptr, g_H);

    cudaFuncSetAttribute(gemm_fp16_wmma_kernel,
                         cudaFuncAttributeMaxDynamicSharedMemorySize, SMEM_BYTES);

    const size_t slice = (size_t)NNODES * DDIM;
    const int n4 = (int)(slice / 4);

    // fp16 conversion of inputs + weights
    dim3 convx_grid((n4 + 255) / 256, 3);
    conv_x_kernel<<<convx_grid, 256>>>(x0, x1, x2, n4);
    conv_b_kernel<<<(DDIM * NCAT + 255) / 256, 256>>>(Wmat, Wres);

    // Norm + CSR build (shared across the 3 convs)
    init_kernel<<<(NNODES + 255) / 256, 256>>>();
    accum_kernel<<<(NEDGES + 255) / 256, 256>>>(dst, w);
    calc_dis_kernel<<<(NNODES + 255) / 256, 256>>>();
    scan1_kernel<<<SCAN_NB, SCAN_BS>>>();
    scan2_kernel<<<1, 32>>>();
    scan3_kernel<<<(NNODES + 255) / 256, 256>>>();
    fill_kernel<<<(NEDGES + 255) / 256, 256>>>(src, dst, w);

    // One batched GEMM over all 3 inputs: [H_t | O_t] = X_t @ [W | Wres]
    dim3 gemm_grid(8, (NNODES + MT - 1) / MT, 3);
    gemm_fp16_wmma_kernel<<<gemm_grid, 256, SMEM_BYTES>>>(Hptr, out, NNODES);

    // One batched gather/finalize over all 3 convs
    dim3 gather_grid(NNODES, 3);
    gather_finalize_kernel<<<gather_grid, 128>>>(out);
}

// round 7
// speedup vs baseline: 5.2461x; 1.1030x over previous
#include <cuda_runtime.h>
#include <cuda_fp16.h>
#include <mma.h>
#include <cstdint>

using namespace nvcuda;

#define NNODES 50000
#define NEDGES 400000
#define DDIM   512
#define NCAT   1024
#define NEG_SLOPE 0.01f
#define FILL 2.0f

// ---------------------------------------------------------------------------
// Device scratch (static: no allocations allowed)
// ---------------------------------------------------------------------------
__device__ __half g_Xh[(size_t)3 * NNODES * DDIM];  // fp16 inputs (153.6MB)
__device__ __half g_Bh[(size_t)DDIM * NCAT];        // fp16 [W | Wres] (1MB)
__device__ __half g_Hh[(size_t)3 * NNODES * DDIM];  // H_t = X_t @ W (fp16, 153.6MB)
__device__ float  g_deg[NNODES];
__device__ float  g_dis[NNODES];
__device__ int    g_cnt[NNODES];
__device__ int    g_off[NNODES + 1];
__device__ int    g_bsum[128];
__device__ int    g_srcs[NEDGES];
__device__ float  g_coef[NEDGES];

struct alignas(8) half4 { __half2 a, b; };

// ---------------------------------------------------------------------------
// fp32 -> fp16 conversion passes
// ---------------------------------------------------------------------------
__global__ void conv_x_kernel(const float* __restrict__ x0,
                              const float* __restrict__ x1,
                              const float* __restrict__ x2, int n4) {
    int i = blockIdx.x * blockDim.x + threadIdx.x;
    if (i >= n4) return;
    int t = blockIdx.y;
    const float* x = (t == 0) ? x0 : (t == 1) ? x1 : x2;
    float4 v = ((const float4*)x)[i];
    half4 o;
    o.a = __floats2half2_rn(v.x, v.y);
    o.b = __floats2half2_rn(v.z, v.w);
    ((half4*)(g_Xh + (size_t)t * NNODES * DDIM))[i] = o;
}

__global__ void conv_b_kernel(const float* __restrict__ W, const float* __restrict__ Wres) {
    int i = blockIdx.x * blockDim.x + threadIdx.x;
    if (i >= DDIM * NCAT) return;
    int k = i >> 10, n = i & 1023;
    float v = (n < DDIM) ? W[(size_t)k * DDIM + n] : Wres[(size_t)k * DDIM + (n - DDIM)];
    g_Bh[i] = __float2half_rn(v);
}

// ---------------------------------------------------------------------------
// Degree / norm / CSR build
// ---------------------------------------------------------------------------
__global__ void init_kernel() {
    int n = blockIdx.x * blockDim.x + threadIdx.x;
    if (n < NNODES) { g_deg[n] = FILL; g_cnt[n] = 0; }
}
__global__ void accum_kernel(const int* __restrict__ dst, const float* __restrict__ w) {
    int e = blockIdx.x * blockDim.x + threadIdx.x;
    if (e < NEDGES) {
        int d = dst[e];
        atomicAdd(&g_deg[d], w[e]);
        atomicAdd(&g_cnt[d], 1);
    }
}
__global__ void calc_dis_kernel() {
    int n = blockIdx.x * blockDim.x + threadIdx.x;
    if (n < NNODES) {
        float d = g_deg[n];
        g_dis[n] = (d > 0.0f) ? rsqrtf(d) : 0.0f;
    }
}

#define SCAN_BS 512
#define SCAN_NB ((NNODES + SCAN_BS - 1) / SCAN_BS)   // 98

__global__ void scan1_kernel() {
    __shared__ int s[SCAN_BS];
    int tid = threadIdx.x;
    int i = blockIdx.x * SCAN_BS + tid;
    int val = (i < NNODES) ? g_cnt[i] : 0;
    s[tid] = val;
    __syncthreads();
    #pragma unroll
    for (int o = 1; o < SCAN_BS; o <<= 1) {
        int t = (tid >= o) ? s[tid - o] : 0;
        __syncthreads();
        s[tid] += t;
        __syncthreads();
    }
    int incl = s[tid];
    if (i < NNODES) g_off[i] = incl - val;
    if (tid == SCAN_BS - 1) g_bsum[blockIdx.x] = incl;
}
__global__ void scan2_kernel() {
    if (threadIdx.x == 0) {
        int run = 0;
        for (int b = 0; b < SCAN_NB; b++) { int t = g_bsum[b]; g_bsum[b] = run; run += t; }
    }
}
__global__ void scan3_kernel() {
    int i = blockIdx.x * blockDim.x + threadIdx.x;
    if (i < NNODES) { g_off[i] += g_bsum[i >> 9]; g_cnt[i] = 0; }
    if (i == 0) g_off[NNODES] = NEDGES;
}
__global__ void fill_kernel(const int* __restrict__ src, const int* __restrict__ dst,
                            const float* __restrict__ w) {
    int e = blockIdx.x * blockDim.x + threadIdx.x;
    if (e >= NEDGES) return;
    int s = src[e], d = dst[e];
    int pos = atomicAdd(&g_cnt[d], 1);
    int slot = g_off[d] + pos;
    g_srcs[slot] = s;
    g_coef[slot] = g_dis[s] * w[e] * g_dis[d];
}

// ---------------------------------------------------------------------------
// FP16 WMMA GEMM (fp32 accumulate), batched over the 3 inputs via grid.z.
// C_t[M, 1024] = Xh_t[M,512] @ g_Bh. CTA 128x128, BK=32, 8 warps (32x64
// warp tile). H tiles (cols<512) convert to fp16 via smem staging;
// O tiles (cols>=512) store fp32 directly to d_out.
// ---------------------------------------------------------------------------
#define MT 128
#define NT 128
#define BK 32
#define LDA (BK + 8)
#define LDB (NT + 8)
#define A_STAGE (MT * LDA)
#define B_STAGE (BK * LDB)
#define SMEM_BYTES 65536
#define CHUNKS (DDIM / BK)

__global__ __launch_bounds__(256, 2) void gemm_fp16_wmma_kernel(
    float* __restrict__ Obase,       // [3, M, 512] (d_out)
    int M)
{
    extern __shared__ char smem_raw[];
    __half* As = (__half*)smem_raw;
    __half* Bs = As + 2 * A_STAGE;

    const int tid = threadIdx.x;
    const int wid = tid >> 5;
    const int m0 = blockIdx.y * MT;
    const int ncol0 = blockIdx.x * NT;
    const int t = blockIdx.z;

    const __half* A = g_Xh + (size_t)t * M * DDIM;
    const size_t slice = (size_t)M * DDIM;

    const int warp_m = wid & 3;
    const int warp_n = wid >> 2;

    wmma::fragment<wmma::accumulator, 16, 16, 16, float> acc[2][4];
    #pragma unroll
    for (int mi = 0; mi < 2; mi++)
        #pragma unroll
        for (int ni = 0; ni < 4; ni++) wmma::fill_fragment(acc[mi][ni], 0.0f);

    auto load_chunk = [&](int kc, int st) {
        const int k0 = kc * BK;
        __half* a_base = As + st * A_STAGE;
        __half* b_base = Bs + st * B_STAGE;
        #pragma unroll
        for (int i = 0; i < 2; i++) {
            int idx = i * 256 + tid;
            int r = idx >> 2, c = idx & 3;
            int gr = m0 + r;
            const __half* src = A + (size_t)(gr < M ? gr : (M - 1)) * DDIM + k0 + c * 8;
            uint32_t dst;
            asm("{ .reg .u64 t; cvta.to.shared.u64 t, %1; cvt.u32.u64 %0, t; }"
                : "=r"(dst) : "l"(a_base + r * LDA + c * 8));
            int sz = (gr < M) ? 16 : 0;
            asm volatile("cp.async.cg.shared.global [%0], [%1], 16, %2;"
                         :: "r"(dst), "l"(src), "r"(sz));
        }
        #pragma unroll
        for (int i = 0; i < 2; i++) {
            int idx = i * 256 + tid;
            int r = idx >> 4, c = idx & 15;
            const __half* src = g_Bh + (size_t)(k0 + r) * NCAT + ncol0 + c * 8;
            uint32_t dst;
            asm("{ .reg .u64 t; cvta.to.shared.u64 t, %1; cvt.u32.u64 %0, t; }"
                : "=r"(dst) : "l"(b_base + r * LDB + c * 8));
            asm volatile("cp.async.cg.shared.global [%0], [%1], 16;"
                         :: "r"(dst), "l"(src));
        }
        asm volatile("cp.async.commit_group;" ::: "memory");
    };

    load_chunk(0, 0);

    #pragma unroll 1
    for (int kc = 0; kc < CHUNKS; kc++) {
        const int st = kc & 1;
        if (kc + 1 < CHUNKS) {
            load_chunk(kc + 1, st ^ 1);
            asm volatile("cp.async.wait_group 1;" ::: "memory");
        } else {
            asm volatile("cp.async.wait_group 0;" ::: "memory");
        }
        __syncthreads();

        const __half* a_base = As + st * A_STAGE;
        const __half* b_base = Bs + st * B_STAGE;

        #pragma unroll
        for (int ks = 0; ks < BK / 16; ks++) {
            wmma::fragment<wmma::matrix_a, 16, 16, 16, __half, wmma::row_major> af[2];
            wmma::fragment<wmma::matrix_b, 16, 16, 16, __half, wmma::row_major> bf[4];
            #pragma unroll
            for (int mi = 0; mi < 2; mi++)
                wmma::load_matrix_sync(af[mi],
                    a_base + (warp_m * 32 + mi * 16) * LDA + ks * 16, LDA);
            #pragma unroll
            for (int ni = 0; ni < 4; ni++)
                wmma::load_matrix_sync(bf[ni],
                    b_base + (ks * 16) * LDB + warp_n * 64 + ni * 16, LDB);
            #pragma unroll
            for (int mi = 0; mi < 2; mi++)
                #pragma unroll
                for (int ni = 0; ni < 4; ni++)
                    wmma::mma_sync(acc[mi][ni], af[mi], bf[ni], acc[mi][ni]);
        }
        __syncthreads();
    }

    const bool is_h = (ncol0 < DDIM);
    const int oc0 = ncol0 & (DDIM - 1);

    if (is_h) {
        // H tile -> fp16: stage fp32 in smem, convert, write half4 chunks.
        float* sC = (float*)smem_raw;   // 128x128 f32 = 64KB
        #pragma unroll
        for (int mi = 0; mi < 2; mi++)
            #pragma unroll
            for (int ni = 0; ni < 4; ni++) {
                int r = warp_m * 32 + mi * 16;
                int c = warp_n * 64 + ni * 16;
                wmma::store_matrix_sync(sC + r * NT + c, acc[mi][ni], NT,
                                        wmma::mem_row_major);
            }
        __syncthreads();
        __half* Ht = g_Hh + (size_t)t * slice;
        #pragma unroll
        for (int i = 0; i < 16; i++) {
            int idx = i * 256 + tid;
            int r = idx >> 5, c = idx & 31;      // 4 floats at (r, 4c)
            if (m0 + r < M) {
                float4 v = *(const float4*)(sC + r * NT + c * 4);
                half4 h;
                h.a = __floats2half2_rn(v.x, v.y);
                h.b = __floats2half2_rn(v.z, v.w);
                *(half4*)(Ht + (size_t)(m0 + r) * DDIM + oc0 + c * 4) = h;
            }
        }
    } else {
        float* outbase = Obase + t * slice;
        if (m0 + MT <= M) {
            #pragma unroll
            for (int mi = 0; mi < 2; mi++)
                #pragma unroll
                for (int ni = 0; ni < 4; ni++) {
                    int r = m0 + warp_m * 32 + mi * 16;
                    int c = oc0 + warp_n * 64 + ni * 16;
                    wmma::store_matrix_sync(outbase + (size_t)r * DDIM + c,
                                            acc[mi][ni], DDIM, wmma::mem_row_major);
                }
        } else {
            float* sC = (float*)smem_raw;
            #pragma unroll
            for (int mi = 0; mi < 2; mi++)
                #pragma unroll
                for (int ni = 0; ni < 4; ni++) {
                    int r = warp_m * 32 + mi * 16;
                    int c = warp_n * 64 + ni * 16;
                    wmma::store_matrix_sync(sC + r * NT + c, acc[mi][ni], NT,
                                            wmma::mem_row_major);
                }
            __syncthreads();
            #pragma unroll
            for (int i = 0; i < 16; i++) {
                int idx = i * 256 + tid;
                int r = idx >> 5, c = idx & 31;
                if (m0 + r < M) {
                    float4 v = *(const float4*)(sC + r * NT + c * 4);
                    *(float4*)(outbase + (size_t)(m0 + r) * DDIM + oc0 + c * 4) = v;
                }
            }
        }
    }
}

// ---------------------------------------------------------------------------
// Fused gather + self-loop + residual + leaky relu, fp16 H.
// Flat 1D grid ordered t-major so each conv's 51MB H slice stays L2-resident.
// One block per (t, node); thread c handles 4 columns (8B fp16 loads).
// ---------------------------------------------------------------------------
__device__ __forceinline__ void acc_row(const __half* row, int c, float cf,
                                        float& x, float& y, float& z, float& w) {
    half4 v = ((const half4*)row)[c];
    float2 lo = __half22float2(v.a);
    float2 hi = __half22float2(v.b);
    x = fmaf(cf, lo.x, x); y = fmaf(cf, lo.y, y);
    z = fmaf(cf, hi.x, z); w = fmaf(cf, hi.y, w);
}

__global__ __launch_bounds__(128) void gather_finalize_kernel(float* __restrict__ Obase) {
    const int bid = blockIdx.x;
    const int t = bid / NNODES;
    const int n = bid - t * NNODES;
    const int c = threadIdx.x;              // 4-col group index 0..127

    const size_t slice = (size_t)NNODES * DDIM;
    const __half* Ht = g_Hh + t * slice;
    float* O = Obase + t * slice;

    const float dn = g_dis[n];
    const float sc = FILL * dn * dn;

    float ax = 0.f, ay = 0.f, az = 0.f, aw = 0.f;
    float bx = 0.f, by = 0.f, bz = 0.f, bw = 0.f;
    acc_row(Ht + (size_t)n * DDIM, c, sc, ax, ay, az, aw);

    const int beg = g_off[n], end = g_off[n + 1];
    int j = beg;
    for (; j + 1 < end; j += 2) {
        int s0 = g_srcs[j], s1 = g_srcs[j + 1];
        float c0 = g_coef[j], c1 = g_coef[j + 1];
        acc_row(Ht + (size_t)s0 * DDIM, c, c0, ax, ay, az, aw);
        acc_row(Ht + (size_t)s1 * DDIM, c, c1, bx, by, bz, bw);
    }
    if (j < end)
        acc_row(Ht + (size_t)g_srcs[j] * DDIM, c, g_coef[j], ax, ay, az, aw);

    ax += bx; ay += by; az += bz; aw += bw;

    float4* op = (float4*)(O + (size_t)n * DDIM) + c;
    float4 o = *op;
    o.x = o.x + ax; o.x = o.x >= 0.f ? o.x : NEG_SLOPE * o.x;
    o.y = o.y + ay; o.y = o.y >= 0.f ? o.y : NEG_SLOPE * o.y;
    o.z = o.z + az; o.z = o.z >= 0.f ? o.z : NEG_SLOPE * o.z;
    o.w = o.w + aw; o.w = o.w >= 0.f ? o.w : NEG_SLOPE * o.w;
    *op = o;
}

// ---------------------------------------------------------------------------
// Launch
// ---------------------------------------------------------------------------
extern "C" void kernel_launch(void* const* d_in, const int* in_sizes, int n_in,
                              void* d_out, int out_size)
{
    const float* x0   = (const float*)d_in[0];
    const float* x1   = (const float*)d_in[1];
    const float* x2   = (const float*)d_in[2];
    const int*   adj  = (const int*)d_in[3];
    const float* w    = (const float*)d_in[4];
    const float* Wmat = (const float*)d_in[5];
    const float* Wres = (const float*)d_in[6];
    float* out = (float*)d_out;

    const int* src = adj;
    const int* dst = adj + NEDGES;

    cudaFuncSetAttribute(gemm_fp16_wmma_kernel,
                         cudaFuncAttributeMaxDynamicSharedMemorySize, SMEM_BYTES);

    const size_t slice = (size_t)NNODES * DDIM;
    const int n4 = (int)(slice / 4);

    // fp16 conversion of inputs + weights
    dim3 convx_grid((n4 + 255) / 256, 3);
    conv_x_kernel<<<convx_grid, 256>>>(x0, x1, x2, n4);
    conv_b_kernel<<<(DDIM * NCAT + 255) / 256, 256>>>(Wmat, Wres);

    // Norm + CSR build (shared across the 3 convs)
    init_kernel<<<(NNODES + 255) / 256, 256>>>();
    accum_kernel<<<(NEDGES + 255) / 256, 256>>>(dst, w);
    calc_dis_kernel<<<(NNODES + 255) / 256, 256>>>();
    scan1_kernel<<<SCAN_NB, SCAN_BS>>>();
    scan2_kernel<<<1, 32>>>();
    scan3_kernel<<<(NNODES + 255) / 256, 256>>>();
    fill_kernel<<<(NEDGES + 255) / 256, 256>>>(src, dst, w);

    // One batched GEMM over all 3 inputs: [H_t | O_t] = X_t @ [W | Wres]
    dim3 gemm_grid(8, (NNODES + MT - 1) / MT, 3);
    gemm_fp16_wmma_kernel<<<gemm_grid, 256, SMEM_BYTES>>>(out, NNODES);

    // One batched gather/finalize, t-major for L2 residency of each H slice
    gather_finalize_kernel<<<3 * NNODES, 128>>>(out);
}